// round 7
// baseline (speedup 1.0000x reference)
#include <cuda_runtime.h>
#include <cuda_bf16.h>
#include <math.h>
#include <stdint.h>

typedef unsigned int u32;

// Problem constants
#define B_ 2
#define Q_ 75
#define N_ 5
#define T_ 196
#define C_ 384
#define D_ 384
#define SCALE (1.0f / 14.0f)

// Tiling
#define TPB 512
#define DT 64
#define NSLAB 6
#define KP1 13           // GEMM1 k16 panels (t: 196->208)
#define KP2 24           // GEMM2 k16 panels (c: 384)
#define NT2 224          // GEMM2 N (t padded)

// packed panel sizes (u32 words)
#define A1_PANEL 1024    // [pl2][T4][lane32][reg4]
#define B1_PANEL 6144    // [pl2][G48][lane32][reg2]
#define B2_PANEL 3584    // [pl2][G28][lane32][reg2]

__device__ u32 g_A1[150 * NSLAB * KP1 * A1_PANEL];  // ~48 MB
__device__ u32 g_B1[10 * KP1 * B1_PANEL];           // ~3.2 MB
__device__ u32 g_B2[150 * KP2 * B2_PANEL];          // ~49.2 MB
__device__ float g_top1[B_ * Q_ * N_];

// smem layout (u32 offsets)
#define U_A2   0                        // A2 frags [p24][pl2][T4][reg4][lane32] = 24576
#define U_B    24576                    // B staging dbuf: 2*6144
#define U_A1   (U_B + 2 * B1_PANEL)     // 36864: A1 dbuf 2*1024
#define U_PN   (U_A1 + 2 * A1_PANEL)    // 38912: [2][224]
#define U_PQ   (U_PN + 2 * NT2)         // 39360
#define U_RINV (U_PQ + 2 * NT2)         // 39808: [64]
#define U_PMAX (U_RINV + 64)            // 39872: [64][8]
#define U_PSUM (U_PMAX + 512)           // 40384
#define U_NFS  (U_PSUM + 512)           // 40896: [224]
#define U_RED  (U_NFS + NT2)            // 41120: [16]
#define U_TOT  (U_RED + 16)             // 41136 u32 = 164544 B

__device__ __forceinline__ u32 bpack_hi(float x0, float x1) {
    __nv_bfloat162 h;
    h.x = __float2bfloat16(x0);
    h.y = __float2bfloat16(x1);
    return *(u32*)&h;
}
__device__ __forceinline__ u32 bpack_lo(float x0, float x1) {
    __nv_bfloat16 h0 = __float2bfloat16(x0);
    __nv_bfloat16 h1 = __float2bfloat16(x1);
    __nv_bfloat162 l;
    l.x = __float2bfloat16(x0 - __bfloat162float(h0));
    l.y = __float2bfloat16(x1 - __bfloat162float(h1));
    return *(u32*)&l;
}
__device__ __forceinline__ void bsplit2(float x0, float x1, u32& hw, u32& lw) {
    __nv_bfloat16 h0 = __float2bfloat16(x0);
    __nv_bfloat16 h1 = __float2bfloat16(x1);
    __nv_bfloat162 hh; hh.x = h0; hh.y = h1;
    hw = *(u32*)&hh;
    __nv_bfloat162 ll;
    ll.x = __float2bfloat16(x0 - __bfloat162float(h0));
    ll.y = __float2bfloat16(x1 - __bfloat162float(h1));
    lw = *(u32*)&ll;
}

__device__ __forceinline__ void mma16(float* c, const u32* a, u32 b0, u32 b1) {
    asm volatile(
        "mma.sync.aligned.m16n8k16.row.col.f32.bf16.bf16.f32 "
        "{%0,%1,%2,%3},{%4,%5,%6,%7},{%8,%9},{%0,%1,%2,%3};"
        : "+f"(c[0]), "+f"(c[1]), "+f"(c[2]), "+f"(c[3])
        : "r"(a[0]), "r"(a[1]), "r"(a[2]), "r"(a[3]), "r"(b0), "r"(b1));
}

__device__ __forceinline__ void cp16(u32 daddr, const void* src) {
    asm volatile("cp.async.cg.shared.global [%0], [%1], 16;" :: "r"(daddr), "l"(src));
}
#define CP_COMMIT() asm volatile("cp.async.commit_group;" ::: "memory")
#define CP_WAIT0()  asm volatile("cp.async.wait_group 0;" ::: "memory")

// ==================== pack kernels ====================

// A1[m=d][k=t] = SCALE * Fq[t][d], fragment dump per (bq, slab, panel)
// layout: [pl2][T4][lane32][reg4]
__global__ void pack_a1(const float* __restrict__ fq) {
    __shared__ float tile[16][65];
    int bid = blockIdx.x;                 // (bq*NSLAB+s)*KP1 + p
    int p  = bid % KP1;
    int s  = (bid / KP1) % NSLAB;
    int bq = bid / (KP1 * NSLAB);
    const float* Fq = fq + (size_t)bq * T_ * C_;
    int d0 = s * DT;
    for (int idx = threadIdx.x; idx < 16 * DT; idx += 256) {
        int k = idx >> 6, d = idx & 63;
        int t = p * 16 + k;
        tile[k][d] = (t < T_) ? SCALE * Fq[(size_t)t * C_ + d0 + d] : 0.f;
    }
    __syncthreads();
    u32* dst = g_A1 + (size_t)bid * A1_PANEL;
    for (int idx = threadIdx.x; idx < A1_PANEL; idx += 256) {
        int pl  = idx >> 9;
        int rem = idx & 511;
        int T   = rem >> 7;
        int lane = (rem >> 2) & 31;
        int reg  = idx & 3;
        int grr = lane >> 2, gcc = lane & 3;
        int dl = T * 16 + grr + ((reg & 1) ? 8 : 0);
        int kl = 2 * gcc + ((reg & 2) ? 8 : 0);
        float x0 = tile[kl][dl], x1 = tile[kl + 1][dl];
        dst[idx] = pl ? bpack_lo(x0, x1) : bpack_hi(x0, x1);
    }
}

// B1[k=t][n=c] = Fs[t][c], fragment dump per (bn, panel)
__global__ void pack_b1(const float* __restrict__ fs) {
    __shared__ float tile[16][385];
    int bid = blockIdx.x;                 // bn*KP1 + p
    int p  = bid % KP1;
    int bn = bid / KP1;
    const float* Fs = fs + (size_t)bn * T_ * C_;
    for (int idx = threadIdx.x; idx < 16 * C_; idx += 256) {
        int k = idx / C_, c = idx % C_;
        int t = p * 16 + k;
        tile[k][c] = (t < T_) ? Fs[(size_t)t * C_ + c] : 0.f;
    }
    __syncthreads();
    u32* dst = g_B1 + (size_t)bid * B1_PANEL;
    for (int idx = threadIdx.x; idx < B1_PANEL; idx += 256) {
        int pl  = idx / 3072;
        int rem = idx % 3072;
        int G   = rem >> 6;
        int lane = (rem >> 1) & 31;
        int reg  = idx & 1;
        int grr = lane >> 2, gcc = lane & 3;
        int n  = G * 8 + grr;
        int kl = 2 * gcc + 8 * reg;
        float x0 = tile[kl][n], x1 = tile[kl + 1][n];
        dst[idx] = pl ? bpack_lo(x0, x1) : bpack_hi(x0, x1);
    }
}

// B2[k=c][n=t] = Fq[t][c], fragment dump per (bq, panel)
__global__ void pack_b2(const float* __restrict__ fq) {
    __shared__ float tile[T_][17];
    int bid = blockIdx.x;                 // bq*KP2 + p
    int p  = bid % KP2;
    int bq = bid / KP2;
    const float* Fq = fq + (size_t)bq * T_ * C_;
    for (int idx = threadIdx.x; idx < T_ * 16; idx += 256) {
        int t = idx >> 4, c = idx & 15;
        tile[t][c] = Fq[(size_t)t * C_ + p * 16 + c];
    }
    __syncthreads();
    u32* dst = g_B2 + (size_t)bid * B2_PANEL;
    for (int idx = threadIdx.x; idx < B2_PANEL; idx += 256) {
        int pl  = idx / 1792;
        int rem = idx % 1792;
        int G   = rem >> 6;
        int lane = (rem >> 1) & 31;
        int reg  = idx & 1;
        int grr = lane >> 2, gcc = lane & 3;
        int t  = G * 8 + grr;
        int kl = 2 * gcc + 8 * reg;
        float x0 = 0.f, x1 = 0.f;
        if (t < T_) { x0 = tile[t][kl]; x1 = tile[t][kl + 1]; }
        dst[idx] = pl ? bpack_lo(x0, x1) : bpack_hi(x0, x1);
    }
}

// ==================== main kernel ====================

__global__ __launch_bounds__(TPB, 1)
void episodic_main(const float* __restrict__ fs_g) {
    extern __shared__ u32 smu[];
    float* smf = (float*)smu;
    const u32 smbase = (u32)__cvta_generic_to_shared(smu);

    const int bx = blockIdx.x;
    const int nn = bx % N_;
    const int bq = bx / N_;          // b*75+q
    const int bb = bq / Q_;
    const int bn = bb * N_ + nn;
    const float* __restrict__ Fs = fs_g + (size_t)bn * T_ * C_;

    const int tid = threadIdx.x;
    const int wid = tid >> 5, lane = tid & 31;
    const int wm = wid >> 3, wn = wid & 7;   // wm: 0..1, wn: 0..7
    const int gr = lane >> 2, gc = lane & 3;
    // GEMM2 uneven N split: wn<4 -> 4 G groups, wn>=4 -> 3 G groups
    const int ng2 = (wn < 4) ? 4 : 3;
    const int g2base = (wn < 4) ? wn * 4 : 16 + (wn - 4) * 3;

    // init partials + Fs token norms
    for (int i = tid; i < 2 * NT2; i += TPB) { smf[U_PN + i] = 0.f; smf[U_PQ + i] = 0.f; }
    for (int r = wid; r < T_; r += 16) {
        float s = 0.f;
        #pragma unroll
        for (int u = 0; u < 12; u++) {
            float v = Fs[(size_t)r * C_ + lane + 32 * u];
            s += v * v;
        }
        #pragma unroll
        for (int o = 16; o > 0; o >>= 1) s += __shfl_xor_sync(0xffffffffu, s, o);
        if (lane == 0) smf[U_NFS + r] = sqrtf(s);
    }
    __syncthreads();

    const u32* gB1 = g_B1 + (size_t)bn * KP1 * B1_PANEL;
    const u32* gB2 = g_B2 + (size_t)bq * KP2 * B2_PANEL;

    for (int slab = 0; slab < NSLAB; slab++) {
        const int d0 = slab * DT;
        const u32* gA1 = g_A1 + (size_t)(bq * NSLAB + slab) * KP1 * A1_PANEL;

        // ---------------- GEMM1: S[64][384] ----------------
        float acc1[2][6][4];
        #pragma unroll
        for (int mt = 0; mt < 2; mt++)
            #pragma unroll
            for (int nt = 0; nt < 6; nt++)
                #pragma unroll
                for (int e = 0; e < 4; e++) acc1[mt][nt][e] = 0.f;

        // prefetch panel 0
        {
            const float4* srcB = (const float4*)(gB1);
            u32 dstB = smbase + (U_B) * 4;
            #pragma unroll
            for (int j = 0; j < 3; j++) cp16(dstB + (tid + j * TPB) * 16, srcB + tid + j * TPB);
            if (tid < 256) {
                const float4* srcA = (const float4*)(gA1);
                cp16(smbase + (U_A1) * 4 + tid * 16, srcA + tid);
            }
            CP_COMMIT();
        }
        for (int p = 0; p < KP1; p++) {
            const int buf = p & 1;
            CP_WAIT0();
            __syncthreads();
            if (p + 1 < KP1) {
                const float4* srcB = (const float4*)(gB1 + (size_t)(p + 1) * B1_PANEL);
                u32 dstB = smbase + (U_B + (buf ^ 1) * B1_PANEL) * 4;
                #pragma unroll
                for (int j = 0; j < 3; j++) cp16(dstB + (tid + j * TPB) * 16, srcB + tid + j * TPB);
                if (tid < 256) {
                    const float4* srcA = (const float4*)(gA1 + (size_t)(p + 1) * A1_PANEL);
                    cp16(smbase + (U_A1 + (buf ^ 1) * A1_PANEL) * 4 + tid * 16, srcA + tid);
                }
                CP_COMMIT();
            }
            const u32* bA = smu + U_A1 + buf * A1_PANEL;
            const u32* bB = smu + U_B + buf * B1_PANEL;
            u32 ah[2][4], al[2][4];
            #pragma unroll
            for (int mt = 0; mt < 2; mt++) {
                int T = wm * 2 + mt;
                uint4 h = *(const uint4*)&bA[((0 * 4 + T) * 32 + lane) * 4];
                uint4 l = *(const uint4*)&bA[((1 * 4 + T) * 32 + lane) * 4];
                ah[mt][0] = h.x; ah[mt][1] = h.y; ah[mt][2] = h.z; ah[mt][3] = h.w;
                al[mt][0] = l.x; al[mt][1] = l.y; al[mt][2] = l.z; al[mt][3] = l.w;
            }
            #pragma unroll
            for (int nt = 0; nt < 6; nt++) {
                int G = wn * 6 + nt;
                uint2 bh = *(const uint2*)&bB[((0 * 48 + G) * 32 + lane) * 2];
                uint2 bl = *(const uint2*)&bB[((1 * 48 + G) * 32 + lane) * 2];
                #pragma unroll
                for (int mt = 0; mt < 2; mt++) {
                    mma16(acc1[mt][nt], ah[mt], bh.x, bh.y);
                    mma16(acc1[mt][nt], ah[mt], bl.x, bl.y);
                    mma16(acc1[mt][nt], al[mt], bh.x, bh.y);
                }
            }
        }

        // ---------------- softmax (row max/sum across 8 wn-warps) ----------------
        #pragma unroll
        for (int mt = 0; mt < 2; mt++)
            #pragma unroll
            for (int h = 0; h < 2; h++) {
                float mx = -INFINITY;
                #pragma unroll
                for (int nt = 0; nt < 6; nt++)
                    mx = fmaxf(mx, fmaxf(acc1[mt][nt][2 * h], acc1[mt][nt][2 * h + 1]));
                mx = fmaxf(mx, __shfl_xor_sync(0xffffffffu, mx, 1));
                mx = fmaxf(mx, __shfl_xor_sync(0xffffffffu, mx, 2));
                int row = (wm * 2 + mt) * 16 + gr + 8 * h;
                if (gc == 0) smf[U_PMAX + row * 8 + wn] = mx;
            }
        __syncthreads();
        #pragma unroll
        for (int mt = 0; mt < 2; mt++)
            #pragma unroll
            for (int h = 0; h < 2; h++) {
                int row = (wm * 2 + mt) * 16 + gr + 8 * h;
                float gmax = -INFINITY;
                #pragma unroll
                for (int w = 0; w < 8; w++)
                    gmax = fmaxf(gmax, smf[U_PMAX + row * 8 + w]);
                float s = 0.f;
                #pragma unroll
                for (int nt = 0; nt < 6; nt++) {
                    float v0 = __expf(acc1[mt][nt][2 * h] - gmax);
                    float v1 = __expf(acc1[mt][nt][2 * h + 1] - gmax);
                    acc1[mt][nt][2 * h] = v0;
                    acc1[mt][nt][2 * h + 1] = v1;
                    s += v0 + v1;
                }
                s += __shfl_xor_sync(0xffffffffu, s, 1);
                s += __shfl_xor_sync(0xffffffffu, s, 2);
                if (gc == 0) smf[U_PSUM + row * 8 + wn] = s;
            }
        __syncthreads();
        if (wn == 0 && gc == 0) {
            #pragma unroll
            for (int mt = 0; mt < 2; mt++)
                #pragma unroll
                for (int h = 0; h < 2; h++) {
                    int row = (wm * 2 + mt) * 16 + gr + 8 * h;
                    float tot = 0.f;
                    #pragma unroll
                    for (int w = 0; w < 8; w++) tot += smf[U_PSUM + row * 8 + w];
                    smf[U_RINV + row] = 1.0f / tot;
                }
        }

        // pack Pexp into GEMM2 A-fragment layout (C->A frag match; reg-major, conflict-free)
        #pragma unroll
        for (int mt = 0; mt < 2; mt++) {
            int T = wm * 2 + mt;
            #pragma unroll
            for (int nt = 0; nt < 6; nt++) {
                int G = wn * 6 + nt;
                int p2 = G >> 1;
                int rb = (G & 1) * 2;
                u32 hw, lw;
                bsplit2(acc1[mt][nt][0], acc1[mt][nt][1], hw, lw);
                smu[U_A2 + (((p2 * 2 + 0) * 4 + T) * 4 + rb) * 32 + lane] = hw;
                smu[U_A2 + (((p2 * 2 + 1) * 4 + T) * 4 + rb) * 32 + lane] = lw;
                bsplit2(acc1[mt][nt][2], acc1[mt][nt][3], hw, lw);
                smu[U_A2 + (((p2 * 2 + 0) * 4 + T) * 4 + rb + 1) * 32 + lane] = hw;
                smu[U_A2 + (((p2 * 2 + 1) * 4 + T) * 4 + rb + 1) * 32 + lane] = lw;
            }
        }
        __syncthreads();

        // ---------------- GEMM2: fq_new^T[64][224] ----------------
        float acc2[2][4][4];
        #pragma unroll
        for (int mt = 0; mt < 2; mt++)
            #pragma unroll
            for (int nt = 0; nt < 4; nt++)
                #pragma unroll
                for (int e = 0; e < 4; e++) acc2[mt][nt][e] = 0.f;

        {
            const float4* srcB = (const float4*)(gB2);
            u32 dstB = smbase + (U_B) * 4;
            #pragma unroll
            for (int j = 0; j < 2; j++) {
                int i = tid + j * TPB;
                if (i < 896) cp16(dstB + i * 16, srcB + i);
            }
            CP_COMMIT();
        }
        for (int p = 0; p < KP2; p++) {
            const int buf = p & 1;
            CP_WAIT0();
            __syncthreads();
            if (p + 1 < KP2) {
                const float4* srcB = (const float4*)(gB2 + (size_t)(p + 1) * B2_PANEL);
                u32 dstB = smbase + (U_B + (buf ^ 1) * B1_PANEL) * 4;
                #pragma unroll
                for (int j = 0; j < 2; j++) {
                    int i = tid + j * TPB;
                    if (i < 896) cp16(dstB + i * 16, srcB + i);
                }
                CP_COMMIT();
            }
            const u32* bB = smu + U_B + buf * B1_PANEL;
            u32 ah[2][4], al[2][4];
            #pragma unroll
            for (int mt = 0; mt < 2; mt++) {
                int T = wm * 2 + mt;
                #pragma unroll
                for (int r = 0; r < 4; r++) {
                    ah[mt][r] = smu[U_A2 + (((p * 2 + 0) * 4 + T) * 4 + r) * 32 + lane];
                    al[mt][r] = smu[U_A2 + (((p * 2 + 1) * 4 + T) * 4 + r) * 32 + lane];
                }
            }
            for (int nt = 0; nt < ng2; nt++) {
                int G = g2base + nt;
                uint2 bh = *(const uint2*)&bB[((0 * 28 + G) * 32 + lane) * 2];
                uint2 bl = *(const uint2*)&bB[((1 * 28 + G) * 32 + lane) * 2];
                #pragma unroll
                for (int mt = 0; mt < 2; mt++) {
                    mma16(acc2[mt][nt], ah[mt], bh.x, bh.y);
                    mma16(acc2[mt][nt], ah[mt], bl.x, bl.y);
                    mma16(acc2[mt][nt], al[mt], bh.x, bh.y);
                }
            }
        }
        __syncthreads();

        // ---------------- epilogue: rinv, num/norm2 partials ----------------
        for (int nt = 0; nt < ng2; nt++) {
            int G = g2base + nt;
            int ta = G * 8 + 2 * gc;
            int tb = ta + 1;
            float pn_a = 0.f, pq_a = 0.f, pn_b = 0.f, pq_b = 0.f;
            #pragma unroll
            for (int mt = 0; mt < 2; mt++) {
                int rb1 = (wm * 2 + mt) * 16 + gr;
                int rb2 = rb1 + 8;
                float r1 = smf[U_RINV + rb1];
                float r2 = smf[U_RINV + rb2];
                float v0 = acc2[mt][nt][0] * r1;
                float v1 = acc2[mt][nt][1] * r1;
                float v2 = acc2[mt][nt][2] * r2;
                float v3 = acc2[mt][nt][3] * r2;
                int gd1 = d0 + rb1, gd2 = d0 + rb2;
                float fa1 = 0.f, fa2 = 0.f, fb1 = 0.f, fb2 = 0.f;
                if (ta < T_) { fa1 = Fs[(size_t)ta * C_ + gd1]; fa2 = Fs[(size_t)ta * C_ + gd2]; }
                if (tb < T_) { fb1 = Fs[(size_t)tb * C_ + gd1]; fb2 = Fs[(size_t)tb * C_ + gd2]; }
                pn_a += v0 * fa1 + v2 * fa2;
                pq_a += v0 * v0 + v2 * v2;
                pn_b += v1 * fb1 + v3 * fb2;
                pq_b += v1 * v1 + v3 * v3;
            }
            #pragma unroll
            for (int o = 4; o <= 16; o <<= 1) {
                pn_a += __shfl_xor_sync(0xffffffffu, pn_a, o);
                pq_a += __shfl_xor_sync(0xffffffffu, pq_a, o);
                pn_b += __shfl_xor_sync(0xffffffffu, pn_b, o);
                pq_b += __shfl_xor_sync(0xffffffffu, pq_b, o);
            }
            if (lane < 4) {
                smf[U_PN + wm * NT2 + ta] += pn_a;
                smf[U_PQ + wm * NT2 + ta] += pq_a;
                smf[U_PN + wm * NT2 + tb] += pn_b;
                smf[U_PQ + wm * NT2 + tb] += pq_b;
            }
        }
        __syncthreads();
    }  // slab loop

    // cosine sim per token, max over tokens
    float local = -INFINITY;
    if (tid < T_) {
        float num = smf[U_PN + tid] + smf[U_PN + NT2 + tid];
        float nrm = smf[U_PQ + tid] + smf[U_PQ + NT2 + tid];
        float denom = fmaxf(sqrtf(nrm) * smf[U_NFS + tid], 1e-8f);
        local = num / denom;
    }
    #pragma unroll
    for (int o = 16; o > 0; o >>= 1)
        local = fmaxf(local, __shfl_xor_sync(0xffffffffu, local, o));
    if (lane == 0) smf[U_RED + wid] = local;
    __syncthreads();
    if (tid == 0) {
        float m = smf[U_RED];
        #pragma unroll
        for (int w = 1; w < 16; w++) m = fmaxf(m, smf[U_RED + w]);
        g_top1[bx] = m;
    }
}

// ==================== epilogue kernels ====================

__global__ void finalize_logits_kernel(float* __restrict__ out) {
    int i = blockIdx.x * blockDim.x + threadIdx.x;
    if (i < B_ * Q_) {
        float s = 0.f;
        #pragma unroll
        for (int n = 0; n < N_; n++) s += g_top1[i * N_ + n];
        out[i] = s * (1.0f / N_);
    }
}

__global__ void cls_kernel(const float* __restrict__ xq,
                           const float* __restrict__ xs,
                           float* __restrict__ out) {
    int w = (blockIdx.x * blockDim.x + threadIdx.x) >> 5;
    int lid = threadIdx.x & 31;
    if (w >= B_ * Q_ * N_) return;
    int nn = w % N_;
    int qq = (w / N_) % Q_;
    int bb = w / (N_ * Q_);
    const float* q = xq + (size_t)(bb * Q_ + qq) * D_;
    const float* s = xs + (size_t)(bb * N_ + nn) * D_;
    float dot = 0.f, nq = 0.f, ns = 0.f;
    #pragma unroll
    for (int u = 0; u < D_ / 32; u++) {
        float a = q[lid + 32 * u];
        float b = s[lid + 32 * u];
        dot += a * b;
        nq += a * a;
        ns += b * b;
    }
    #pragma unroll
    for (int o = 16; o > 0; o >>= 1) {
        dot += __shfl_xor_sync(0xffffffffu, dot, o);
        nq  += __shfl_xor_sync(0xffffffffu, nq, o);
        ns  += __shfl_xor_sync(0xffffffffu, ns, o);
    }
    if (lid == 0) {
        float den = fmaxf(sqrtf(nq), 1e-12f) * fmaxf(sqrtf(ns), 1e-12f);
        out[B_ * Q_ + w] = 10.0f * dot / den;
    }
}

extern "C" void kernel_launch(void* const* d_in, const int* in_sizes, int n_in,
                              void* d_out, int out_size) {
    const float* fq = (const float*)d_in[0];  // (2,75,196,384)
    const float* fs = (const float*)d_in[1];  // (2,5,1,196,384)
    const float* xq = (const float*)d_in[2];  // (2,75,384)
    const float* xs = (const float*)d_in[3];  // (2,5,1,384)
    float* out = (float*)d_out;               // [150 logits][750 cls_logits]

    pack_a1<<<150 * NSLAB * KP1, 256>>>(fq);
    pack_b1<<<10 * KP1, 256>>>(fs);
    pack_b2<<<150 * KP2, 256>>>(fq);

    const size_t smem_bytes = (size_t)U_TOT * sizeof(u32);
    cudaFuncSetAttribute(episodic_main,
                         cudaFuncAttributeMaxDynamicSharedMemorySize,
                         (int)smem_bytes);
    episodic_main<<<B_ * Q_ * N_, TPB, smem_bytes>>>(fs);

    finalize_logits_kernel<<<1, 256>>>(out);
    cls_kernel<<<(B_ * Q_ * N_ * 32 + 255) / 256, 256>>>(xq, xs, out);
}

// round 8
// speedup vs baseline: 1.1770x; 1.1770x over previous
#include <cuda_runtime.h>
#include <cuda_bf16.h>
#include <math.h>
#include <stdint.h>

typedef unsigned int u32;

// Problem constants
#define B_ 2
#define Q_ 75
#define N_ 5
#define T_ 196
#define C_ 384
#define D_ 384
#define SCALE (1.0f / 14.0f)

// Tiling
#define TPB 256
#define DT 32
#define NSLAB 12
#define KP1 13           // GEMM1 k16 panels (t: 196->208)
#define KP2 24           // GEMM2 k16 panels (c: 384)
#define NT2 224          // GEMM2 N (t padded)

// packed panel sizes (u32 words)
#define A1_PANEL 512     // [pl2][T2][lane32][reg4]
#define B1_PANEL 6144    // [G48][lane32][bh0,bh1,bl0,bl1]
#define B2_PANEL 3584    // [G28][lane32][bh0,bh1,bl0,bl1]

__device__ u32 g_A1[150 * NSLAB * KP1 * A1_PANEL];  // ~45.7 MB
__device__ u32 g_B1[10 * KP1 * B1_PANEL];           // ~3.2 MB
__device__ u32 g_B2[150 * KP2 * B2_PANEL];          // ~49.2 MB
__device__ float g_top1[B_ * Q_ * N_];

// smem layout (u32 offsets)
#define U_A2   0                        // A2 frags [p24][pl2][T2][lane32][r4] = 12288
#define U_B    12288                    // B staging dbuf: 2*6144
#define U_A1   (U_B + 2 * B1_PANEL)     // 24576: A1 dbuf 2*512
#define U_PN   (U_A1 + 2 * A1_PANEL)    // 25600: [224]
#define U_PQ   (U_PN + NT2)             // 25824
#define U_RINV (U_PQ + NT2)             // 26048: [32]
#define U_PMAX (U_RINV + 32)            // 26080: [32][8]
#define U_PSUM (U_PMAX + 256)           // 26336
#define U_NFS  (U_PSUM + 256)           // 26592: [224]
#define U_RED  (U_NFS + NT2)            // 26816: [8]
#define U_TOT  (U_RED + 8)              // 26824 u32 = 107296 B  (2 CTAs = 214.6 KB)

__device__ __forceinline__ u32 bpack_hi(float x0, float x1) {
    __nv_bfloat162 h;
    h.x = __float2bfloat16(x0);
    h.y = __float2bfloat16(x1);
    return *(u32*)&h;
}
__device__ __forceinline__ u32 bpack_lo(float x0, float x1) {
    __nv_bfloat16 h0 = __float2bfloat16(x0);
    __nv_bfloat16 h1 = __float2bfloat16(x1);
    __nv_bfloat162 l;
    l.x = __float2bfloat16(x0 - __bfloat162float(h0));
    l.y = __float2bfloat16(x1 - __bfloat162float(h1));
    return *(u32*)&l;
}
__device__ __forceinline__ void bsplit2(float x0, float x1, u32& hw, u32& lw) {
    __nv_bfloat16 h0 = __float2bfloat16(x0);
    __nv_bfloat16 h1 = __float2bfloat16(x1);
    __nv_bfloat162 hh; hh.x = h0; hh.y = h1;
    hw = *(u32*)&hh;
    __nv_bfloat162 ll;
    ll.x = __float2bfloat16(x0 - __bfloat162float(h0));
    ll.y = __float2bfloat16(x1 - __bfloat162float(h1));
    lw = *(u32*)&ll;
}

__device__ __forceinline__ void mma16(float* c, const u32* a, u32 b0, u32 b1) {
    asm volatile(
        "mma.sync.aligned.m16n8k16.row.col.f32.bf16.bf16.f32 "
        "{%0,%1,%2,%3},{%4,%5,%6,%7},{%8,%9},{%0,%1,%2,%3};"
        : "+f"(c[0]), "+f"(c[1]), "+f"(c[2]), "+f"(c[3])
        : "r"(a[0]), "r"(a[1]), "r"(a[2]), "r"(a[3]), "r"(b0), "r"(b1));
}

__device__ __forceinline__ void cp16(u32 daddr, const void* src) {
    asm volatile("cp.async.cg.shared.global [%0], [%1], 16;" :: "r"(daddr), "l"(src));
}
#define CP_COMMIT() asm volatile("cp.async.commit_group;" ::: "memory")
#define CP_WAIT0()  asm volatile("cp.async.wait_group 0;" ::: "memory")

// ==================== pack kernels ====================

// A1[m=d][k=t] = SCALE * Fq[t][d], fragment dump per (bq, slab, panel)
// layout: [pl2][T2][lane32][reg4]
__global__ void pack_a1(const float* __restrict__ fq) {
    __shared__ float tile[16][33];
    int bid = blockIdx.x;                 // (bq*NSLAB+s)*KP1 + p
    int p  = bid % KP1;
    int s  = (bid / KP1) % NSLAB;
    int bq = bid / (KP1 * NSLAB);
    const float* Fq = fq + (size_t)bq * T_ * C_;
    int d0 = s * DT;
    for (int idx = threadIdx.x; idx < 16 * DT; idx += 256) {
        int k = idx >> 5, d = idx & 31;
        int t = p * 16 + k;
        tile[k][d] = (t < T_) ? SCALE * Fq[(size_t)t * C_ + d0 + d] : 0.f;
    }
    __syncthreads();
    u32* dst = g_A1 + (size_t)bid * A1_PANEL;
    for (int idx = threadIdx.x; idx < A1_PANEL; idx += 256) {
        int pl  = idx >> 8;
        int rem = idx & 255;
        int T   = rem >> 7;
        int lane = (rem >> 2) & 31;
        int reg  = idx & 3;
        int grr = lane >> 2, gcc = lane & 3;
        int dl = T * 16 + grr + ((reg & 1) ? 8 : 0);
        int kl = 2 * gcc + ((reg & 2) ? 8 : 0);
        float x0 = tile[kl][dl], x1 = tile[kl + 1][dl];
        dst[idx] = pl ? bpack_lo(x0, x1) : bpack_hi(x0, x1);
    }
}

// B1[k=t][n=c] = Fs[t][c], fragment dump per (bn, panel)
// layout: [G48][lane32][j4]  j: 0,1 = hi regs; 2,3 = lo regs
__global__ void pack_b1(const float* __restrict__ fs) {
    __shared__ float tile[16][385];
    int bid = blockIdx.x;                 // bn*KP1 + p
    int p  = bid % KP1;
    int bn = bid / KP1;
    const float* Fs = fs + (size_t)bn * T_ * C_;
    for (int idx = threadIdx.x; idx < 16 * C_; idx += 256) {
        int k = idx / C_, c = idx % C_;
        int t = p * 16 + k;
        tile[k][c] = (t < T_) ? Fs[(size_t)t * C_ + c] : 0.f;
    }
    __syncthreads();
    u32* dst = g_B1 + (size_t)bid * B1_PANEL;
    for (int idx = threadIdx.x; idx < B1_PANEL; idx += 256) {
        int G    = idx >> 7;
        int lane = (idx >> 2) & 31;
        int j    = idx & 3;
        int pl   = j >> 1;
        int reg  = j & 1;
        int grr = lane >> 2, gcc = lane & 3;
        int n  = G * 8 + grr;
        int kl = 2 * gcc + 8 * reg;
        float x0 = tile[kl][n], x1 = tile[kl + 1][n];
        dst[idx] = pl ? bpack_lo(x0, x1) : bpack_hi(x0, x1);
    }
}

// B2[k=c][n=t] = Fq[t][c], fragment dump per (bq, panel)
// layout: [G28][lane32][j4]
__global__ void pack_b2(const float* __restrict__ fq) {
    __shared__ float tile[T_][17];
    int bid = blockIdx.x;                 // bq*KP2 + p
    int p  = bid % KP2;
    int bq = bid / KP2;
    const float* Fq = fq + (size_t)bq * T_ * C_;
    for (int idx = threadIdx.x; idx < T_ * 16; idx += 256) {
        int t = idx >> 4, c = idx & 15;
        tile[t][c] = Fq[(size_t)t * C_ + p * 16 + c];
    }
    __syncthreads();
    u32* dst = g_B2 + (size_t)bid * B2_PANEL;
    for (int idx = threadIdx.x; idx < B2_PANEL; idx += 256) {
        int G    = idx >> 7;
        int lane = (idx >> 2) & 31;
        int j    = idx & 3;
        int pl   = j >> 1;
        int reg  = j & 1;
        int grr = lane >> 2, gcc = lane & 3;
        int t  = G * 8 + grr;
        int kl = 2 * gcc + 8 * reg;
        float x0 = 0.f, x1 = 0.f;
        if (t < T_) { x0 = tile[t][kl]; x1 = tile[t][kl + 1]; }
        dst[idx] = pl ? bpack_lo(x0, x1) : bpack_hi(x0, x1);
    }
}

// ==================== main kernel ====================

__global__ __launch_bounds__(TPB, 2)
void episodic_main(const float* __restrict__ fs_g) {
    extern __shared__ u32 smu[];
    float* smf = (float*)smu;
    const u32 smbase = (u32)__cvta_generic_to_shared(smu);

    const int bx = blockIdx.x;
    const int nn = bx % N_;
    const int bq = bx / N_;          // b*75+q
    const int bb = bq / Q_;
    const int bn = bb * N_ + nn;
    const float* __restrict__ Fs = fs_g + (size_t)bn * T_ * C_;

    const int tid = threadIdx.x;
    const int wid = tid >> 5, lane = tid & 31;
    const int gr = lane >> 2, gc = lane & 3;
    // wid = n-split warp index (0..7); each warp owns both m16 tiles.
    // GEMM2 uneven N split: wid<4 -> 4 G groups, wid>=4 -> 3 G groups
    const int ng2 = (wid < 4) ? 4 : 3;
    const int g2base = (wid < 4) ? wid * 4 : 16 + (wid - 4) * 3;

    // init partials + Fs token norms
    for (int i = tid; i < NT2; i += TPB) { smf[U_PN + i] = 0.f; smf[U_PQ + i] = 0.f; }
    for (int r = wid; r < T_; r += 8) {
        float s = 0.f;
        #pragma unroll
        for (int u = 0; u < 12; u++) {
            float v = Fs[(size_t)r * C_ + lane + 32 * u];
            s += v * v;
        }
        #pragma unroll
        for (int o = 16; o > 0; o >>= 1) s += __shfl_xor_sync(0xffffffffu, s, o);
        if (lane == 0) smf[U_NFS + r] = sqrtf(s);
    }
    __syncthreads();

    const u32* gB1 = g_B1 + (size_t)bn * KP1 * B1_PANEL;
    const u32* gB2 = g_B2 + (size_t)bq * KP2 * B2_PANEL;

    for (int slab = 0; slab < NSLAB; slab++) {
        const int d0 = slab * DT;
        const u32* gA1 = g_A1 + (size_t)(bq * NSLAB + slab) * KP1 * A1_PANEL;

        // ---------------- GEMM1: S[32][384] ----------------
        float acc1[2][6][4];
        #pragma unroll
        for (int mt = 0; mt < 2; mt++)
            #pragma unroll
            for (int nt = 0; nt < 6; nt++)
                #pragma unroll
                for (int e = 0; e < 4; e++) acc1[mt][nt][e] = 0.f;

        // prefetch panel 0
        {
            const float4* srcB = (const float4*)(gB1);
            u32 dstB = smbase + (U_B) * 4;
            #pragma unroll
            for (int j = 0; j < 6; j++) cp16(dstB + (tid + j * TPB) * 16, srcB + tid + j * TPB);
            if (tid < 128) {
                const float4* srcA = (const float4*)(gA1);
                cp16(smbase + (U_A1) * 4 + tid * 16, srcA + tid);
            }
            CP_COMMIT();
        }
        for (int p = 0; p < KP1; p++) {
            const int buf = p & 1;
            CP_WAIT0();
            __syncthreads();
            if (p + 1 < KP1) {
                const float4* srcB = (const float4*)(gB1 + (size_t)(p + 1) * B1_PANEL);
                u32 dstB = smbase + (U_B + (buf ^ 1) * B1_PANEL) * 4;
                #pragma unroll
                for (int j = 0; j < 6; j++) cp16(dstB + (tid + j * TPB) * 16, srcB + tid + j * TPB);
                if (tid < 128) {
                    const float4* srcA = (const float4*)(gA1 + (size_t)(p + 1) * A1_PANEL);
                    cp16(smbase + (U_A1 + (buf ^ 1) * A1_PANEL) * 4 + tid * 16, srcA + tid);
                }
                CP_COMMIT();
            }
            const u32* bA = smu + U_A1 + buf * A1_PANEL;
            const u32* bB = smu + U_B + buf * B1_PANEL;
            u32 ah[2][4], al[2][4];
            #pragma unroll
            for (int mt = 0; mt < 2; mt++) {
                uint4 h = *(const uint4*)&bA[((0 * 2 + mt) * 32 + lane) * 4];
                uint4 l = *(const uint4*)&bA[((1 * 2 + mt) * 32 + lane) * 4];
                ah[mt][0] = h.x; ah[mt][1] = h.y; ah[mt][2] = h.z; ah[mt][3] = h.w;
                al[mt][0] = l.x; al[mt][1] = l.y; al[mt][2] = l.z; al[mt][3] = l.w;
            }
            #pragma unroll
            for (int nt = 0; nt < 6; nt++) {
                int G = wid * 6 + nt;
                uint4 b4 = *(const uint4*)&bB[(G * 32 + lane) * 4];
                #pragma unroll
                for (int mt = 0; mt < 2; mt++) {
                    mma16(acc1[mt][nt], ah[mt], b4.x, b4.y);
                    mma16(acc1[mt][nt], ah[mt], b4.z, b4.w);
                    mma16(acc1[mt][nt], al[mt], b4.x, b4.y);
                }
            }
        }

        // ---------------- softmax (row max/sum across 8 warps) ----------------
        #pragma unroll
        for (int mt = 0; mt < 2; mt++)
            #pragma unroll
            for (int h = 0; h < 2; h++) {
                float mx = -INFINITY;
                #pragma unroll
                for (int nt = 0; nt < 6; nt++)
                    mx = fmaxf(mx, fmaxf(acc1[mt][nt][2 * h], acc1[mt][nt][2 * h + 1]));
                mx = fmaxf(mx, __shfl_xor_sync(0xffffffffu, mx, 1));
                mx = fmaxf(mx, __shfl_xor_sync(0xffffffffu, mx, 2));
                int row = mt * 16 + gr + 8 * h;
                if (gc == 0) smf[U_PMAX + row * 8 + wid] = mx;
            }
        __syncthreads();
        #pragma unroll
        for (int mt = 0; mt < 2; mt++)
            #pragma unroll
            for (int h = 0; h < 2; h++) {
                int row = mt * 16 + gr + 8 * h;
                float gmax = -INFINITY;
                #pragma unroll
                for (int w = 0; w < 8; w++)
                    gmax = fmaxf(gmax, smf[U_PMAX + row * 8 + w]);
                float s = 0.f;
                #pragma unroll
                for (int nt = 0; nt < 6; nt++) {
                    float v0 = __expf(acc1[mt][nt][2 * h] - gmax);
                    float v1 = __expf(acc1[mt][nt][2 * h + 1] - gmax);
                    acc1[mt][nt][2 * h] = v0;
                    acc1[mt][nt][2 * h + 1] = v1;
                    s += v0 + v1;
                }
                s += __shfl_xor_sync(0xffffffffu, s, 1);
                s += __shfl_xor_sync(0xffffffffu, s, 2);
                if (gc == 0) smf[U_PSUM + row * 8 + wid] = s;
            }
        __syncthreads();
        if (wid == 0 && gc == 0) {
            #pragma unroll
            for (int mt = 0; mt < 2; mt++)
                #pragma unroll
                for (int h = 0; h < 2; h++) {
                    int row = mt * 16 + gr + 8 * h;
                    float tot = 0.f;
                    #pragma unroll
                    for (int w = 0; w < 8; w++) tot += smf[U_PSUM + row * 8 + w];
                    smf[U_RINV + row] = 1.0f / tot;
                }
        }

        // pack Pexp into GEMM2 A-fragment layout, hi/lo, STS.128 per (p,pl,mt)
        // A2 word idx: (((p*2+pl)*2 + mt)*32 + lane)*4 + r,  r = 2*(G&1) + h
        #pragma unroll
        for (int mt = 0; mt < 2; mt++) {
            #pragma unroll
            for (int np = 0; np < 3; np++) {   // nt pairs (2np, 2np+1) -> panel p
                int G0 = wid * 6 + 2 * np;
                int p  = G0 >> 1;              // G0 even
                u32 vh[4], vl[4];
                bsplit2(acc1[mt][2 * np][0], acc1[mt][2 * np][1], vh[0], vl[0]);
                bsplit2(acc1[mt][2 * np][2], acc1[mt][2 * np][3], vh[1], vl[1]);
                bsplit2(acc1[mt][2 * np + 1][0], acc1[mt][2 * np + 1][1], vh[2], vl[2]);
                bsplit2(acc1[mt][2 * np + 1][2], acc1[mt][2 * np + 1][3], vh[3], vl[3]);
                *(uint4*)&smu[U_A2 + (((p * 2 + 0) * 2 + mt) * 32 + lane) * 4] =
                    make_uint4(vh[0], vh[1], vh[2], vh[3]);
                *(uint4*)&smu[U_A2 + (((p * 2 + 1) * 2 + mt) * 32 + lane) * 4] =
                    make_uint4(vl[0], vl[1], vl[2], vl[3]);
            }
        }
        __syncthreads();

        // ---------------- GEMM2: fq_new^T[32][224] ----------------
        float acc2[2][4][4];
        #pragma unroll
        for (int mt = 0; mt < 2; mt++)
            #pragma unroll
            for (int nt = 0; nt < 4; nt++)
                #pragma unroll
                for (int e = 0; e < 4; e++) acc2[mt][nt][e] = 0.f;

        {
            const float4* srcB = (const float4*)(gB2);
            u32 dstB = smbase + (U_B) * 4;
            #pragma unroll
            for (int j = 0; j < 4; j++) {
                int i = tid + j * TPB;
                if (i < 896) cp16(dstB + i * 16, srcB + i);
            }
            CP_COMMIT();
        }
        for (int p = 0; p < KP2; p++) {
            const int buf = p & 1;
            CP_WAIT0();
            __syncthreads();
            if (p + 1 < KP2) {
                const float4* srcB = (const float4*)(gB2 + (size_t)(p + 1) * B2_PANEL);
                u32 dstB = smbase + (U_B + (buf ^ 1) * B1_PANEL) * 4;
                #pragma unroll
                for (int j = 0; j < 4; j++) {
                    int i = tid + j * TPB;
                    if (i < 896) cp16(dstB + i * 16, srcB + i);
                }
                CP_COMMIT();
            }
            const u32* bB = smu + U_B + buf * B1_PANEL;
            u32 ah[2][4], al[2][4];
            #pragma unroll
            for (int mt = 0; mt < 2; mt++) {
                uint4 h = *(const uint4*)&smu[U_A2 + (((p * 2 + 0) * 2 + mt) * 32 + lane) * 4];
                uint4 l = *(const uint4*)&smu[U_A2 + (((p * 2 + 1) * 2 + mt) * 32 + lane) * 4];
                ah[mt][0] = h.x; ah[mt][1] = h.y; ah[mt][2] = h.z; ah[mt][3] = h.w;
                al[mt][0] = l.x; al[mt][1] = l.y; al[mt][2] = l.z; al[mt][3] = l.w;
            }
            for (int nt = 0; nt < ng2; nt++) {
                int G = g2base + nt;
                uint4 b4 = *(const uint4*)&bB[(G * 32 + lane) * 4];
                #pragma unroll
                for (int mt = 0; mt < 2; mt++) {
                    mma16(acc2[mt][nt], ah[mt], b4.x, b4.y);
                    mma16(acc2[mt][nt], ah[mt], b4.z, b4.w);
                    mma16(acc2[mt][nt], al[mt], b4.x, b4.y);
                }
            }
        }
        __syncthreads();

        // ---------------- epilogue: rinv, num/norm2 partials ----------------
        for (int nt = 0; nt < ng2; nt++) {
            int G = g2base + nt;
            int ta = G * 8 + 2 * gc;
            int tb = ta + 1;
            float pn_a = 0.f, pq_a = 0.f, pn_b = 0.f, pq_b = 0.f;
            #pragma unroll
            for (int mt = 0; mt < 2; mt++) {
                int rb1 = mt * 16 + gr;
                int rb2 = rb1 + 8;
                float r1 = smf[U_RINV + rb1];
                float r2 = smf[U_RINV + rb2];
                float v0 = acc2[mt][nt][0] * r1;
                float v1 = acc2[mt][nt][1] * r1;
                float v2 = acc2[mt][nt][2] * r2;
                float v3 = acc2[mt][nt][3] * r2;
                int gd1 = d0 + rb1, gd2 = d0 + rb2;
                float fa1 = 0.f, fa2 = 0.f, fb1 = 0.f, fb2 = 0.f;
                if (ta < T_) { fa1 = Fs[(size_t)ta * C_ + gd1]; fa2 = Fs[(size_t)ta * C_ + gd2]; }
                if (tb < T_) { fb1 = Fs[(size_t)tb * C_ + gd1]; fb2 = Fs[(size_t)tb * C_ + gd2]; }
                pn_a += v0 * fa1 + v2 * fa2;
                pq_a += v0 * v0 + v2 * v2;
                pn_b += v1 * fb1 + v3 * fb2;
                pq_b += v1 * v1 + v3 * v3;
            }
            #pragma unroll
            for (int o = 4; o <= 16; o <<= 1) {
                pn_a += __shfl_xor_sync(0xffffffffu, pn_a, o);
                pq_a += __shfl_xor_sync(0xffffffffu, pq_a, o);
                pn_b += __shfl_xor_sync(0xffffffffu, pn_b, o);
                pq_b += __shfl_xor_sync(0xffffffffu, pq_b, o);
            }
            if (lane < 4) {
                smf[U_PN + ta] += pn_a;
                smf[U_PQ + ta] += pq_a;
                smf[U_PN + tb] += pn_b;
                smf[U_PQ + tb] += pq_b;
            }
        }
        __syncthreads();
    }  // slab loop

    // cosine sim per token, max over tokens
    float local = -INFINITY;
    if (tid < T_) {
        float num = smf[U_PN + tid];
        float nrm = smf[U_PQ + tid];
        float denom = fmaxf(sqrtf(nrm) * smf[U_NFS + tid], 1e-8f);
        local = num / denom;
    }
    #pragma unroll
    for (int o = 16; o > 0; o >>= 1)
        local = fmaxf(local, __shfl_xor_sync(0xffffffffu, local, o));
    if (lane == 0) smf[U_RED + wid] = local;
    __syncthreads();
    if (tid == 0) {
        float m = smf[U_RED];
        #pragma unroll
        for (int w = 1; w < 8; w++) m = fmaxf(m, smf[U_RED + w]);
        g_top1[bx] = m;
    }
}

// ==================== epilogue kernels ====================

__global__ void finalize_logits_kernel(float* __restrict__ out) {
    int i = blockIdx.x * blockDim.x + threadIdx.x;
    if (i < B_ * Q_) {
        float s = 0.f;
        #pragma unroll
        for (int n = 0; n < N_; n++) s += g_top1[i * N_ + n];
        out[i] = s * (1.0f / N_);
    }
}

__global__ void cls_kernel(const float* __restrict__ xq,
                           const float* __restrict__ xs,
                           float* __restrict__ out) {
    int w = (blockIdx.x * blockDim.x + threadIdx.x) >> 5;
    int lid = threadIdx.x & 31;
    if (w >= B_ * Q_ * N_) return;
    int nn = w % N_;
    int qq = (w / N_) % Q_;
    int bb = w / (N_ * Q_);
    const float* q = xq + (size_t)(bb * Q_ + qq) * D_;
    const float* s = xs + (size_t)(bb * N_ + nn) * D_;
    float dot = 0.f, nq = 0.f, ns = 0.f;
    #pragma unroll
    for (int u = 0; u < D_ / 32; u++) {
        float a = q[lid + 32 * u];
        float b = s[lid + 32 * u];
        dot += a * b;
        nq += a * a;
        ns += b * b;
    }
    #pragma unroll
    for (int o = 16; o > 0; o >>= 1) {
        dot += __shfl_xor_sync(0xffffffffu, dot, o);
        nq  += __shfl_xor_sync(0xffffffffu, nq, o);
        ns  += __shfl_xor_sync(0xffffffffu, ns, o);
    }
    if (lid == 0) {
        float den = fmaxf(sqrtf(nq), 1e-12f) * fmaxf(sqrtf(ns), 1e-12f);
        out[B_ * Q_ + w] = 10.0f * dot / den;
    }
}

extern "C" void kernel_launch(void* const* d_in, const int* in_sizes, int n_in,
                              void* d_out, int out_size) {
    const float* fq = (const float*)d_in[0];  // (2,75,196,384)
    const float* fs = (const float*)d_in[1];  // (2,5,1,196,384)
    const float* xq = (const float*)d_in[2];  // (2,75,384)
    const float* xs = (const float*)d_in[3];  // (2,5,1,384)
    float* out = (float*)d_out;               // [150 logits][750 cls_logits]

    pack_a1<<<150 * NSLAB * KP1, 256>>>(fq);
    pack_b1<<<10 * KP1, 256>>>(fs);
    pack_b2<<<150 * KP2, 256>>>(fq);

    const size_t smem_bytes = (size_t)U_TOT * sizeof(u32);
    cudaFuncSetAttribute(episodic_main,
                         cudaFuncAttributeMaxDynamicSharedMemorySize,
                         (int)smem_bytes);
    episodic_main<<<B_ * Q_ * N_, TPB, smem_bytes>>>(fs);

    finalize_logits_kernel<<<1, 256>>>(out);
    cls_kernel<<<(B_ * Q_ * N_ * 32 + 255) / 256, 256>>>(xq, xs, out);
}

// round 9
// speedup vs baseline: 1.2776x; 1.0855x over previous
#include <cuda_runtime.h>
#include <cuda_bf16.h>
#include <math.h>
#include <stdint.h>

typedef unsigned int u32;

// Problem constants
#define B_ 2
#define Q_ 75
#define N_ 5
#define T_ 196
#define C_ 384
#define D_ 384
#define SCALE (1.0f / 14.0f)

// Tiling
#define TPB 256
#define DT 32
#define NSLAB 12
#define HSLAB 6          // slabs per CTA (work split in halves)
#define KP1 13           // GEMM1 k16 panels (t: 196->208)
#define KP2 24           // GEMM2 k16 panels (c: 384)
#define NG2 25           // GEMM2 G-groups (t: 196->200)
#define NT2 200          // GEMM2 N (t padded to 200)

// packed panel sizes (u32 words)
#define A1_PANEL 512     // [pl2][T2][lane32][reg4]
#define B1_PANEL 6144    // [G48][lane32][bh0,bh1,bl0,bl1]
#define B2_PANEL 3200    // [G25][lane32][bh0,bh1,bl0,bl1]

__device__ u32 g_A1[150 * NSLAB * KP1 * A1_PANEL];  // ~45.7 MB
__device__ u32 g_B1[10 * KP1 * B1_PANEL];           // ~3.2 MB
__device__ u32 g_B2[150 * KP2 * B2_PANEL];          // ~46 MB
__device__ float g_pn[1500 * NT2];
__device__ float g_pq[1500 * NT2];
__device__ float g_nfs[10 * T_];
__device__ float g_top1[B_ * Q_ * N_];

// smem layout (u32 offsets)
#define U_A2   0                        // A2 frags [p24][pl2][T2][lane32][r4] = 12288
#define U_B    12288                    // B staging dbuf: 2*6144
#define U_A1   (U_B + 2 * B1_PANEL)     // 24576: A1 dbuf 2*512
#define U_PN   (U_A1 + 2 * A1_PANEL)    // 25600: [200]
#define U_PQ   (U_PN + NT2)             // 25800
#define U_RINV (U_PQ + NT2)             // 26000: [32]
#define U_PMAX (U_RINV + 32)            // 26032: [32][8]
#define U_PSUM (U_PMAX + 256)           // 26288
#define U_TOT  (U_PSUM + 256)           // 26544 u32 = 106176 B (2 CTAs = 212.4 KB)

__device__ __forceinline__ u32 bpack_hi(float x0, float x1) {
    __nv_bfloat162 h;
    h.x = __float2bfloat16(x0);
    h.y = __float2bfloat16(x1);
    return *(u32*)&h;
}
__device__ __forceinline__ u32 bpack_lo(float x0, float x1) {
    __nv_bfloat16 h0 = __float2bfloat16(x0);
    __nv_bfloat16 h1 = __float2bfloat16(x1);
    __nv_bfloat162 l;
    l.x = __float2bfloat16(x0 - __bfloat162float(h0));
    l.y = __float2bfloat16(x1 - __bfloat162float(h1));
    return *(u32*)&l;
}
__device__ __forceinline__ void bsplit2(float x0, float x1, u32& hw, u32& lw) {
    __nv_bfloat16 h0 = __float2bfloat16(x0);
    __nv_bfloat16 h1 = __float2bfloat16(x1);
    __nv_bfloat162 hh; hh.x = h0; hh.y = h1;
    hw = *(u32*)&hh;
    __nv_bfloat162 ll;
    ll.x = __float2bfloat16(x0 - __bfloat162float(h0));
    ll.y = __float2bfloat16(x1 - __bfloat162float(h1));
    lw = *(u32*)&ll;
}

__device__ __forceinline__ void mma16(float* c, const u32* a, u32 b0, u32 b1) {
    asm volatile(
        "mma.sync.aligned.m16n8k16.row.col.f32.bf16.bf16.f32 "
        "{%0,%1,%2,%3},{%4,%5,%6,%7},{%8,%9},{%0,%1,%2,%3};"
        : "+f"(c[0]), "+f"(c[1]), "+f"(c[2]), "+f"(c[3])
        : "r"(a[0]), "r"(a[1]), "r"(a[2]), "r"(a[3]), "r"(b0), "r"(b1));
}

__device__ __forceinline__ void cp16(u32 daddr, const void* src) {
    asm volatile("cp.async.cg.shared.global [%0], [%1], 16;" :: "r"(daddr), "l"(src));
}
#define CP_COMMIT() asm volatile("cp.async.commit_group;" ::: "memory")
#define CP_WAIT0()  asm volatile("cp.async.wait_group 0;" ::: "memory")

// ==================== pack kernels ====================

// A1[m=d][k=t] = SCALE * Fq[t][d], fragment dump per (bq, slab, panel)
__global__ void pack_a1(const float* __restrict__ fq) {
    __shared__ float tile[16][33];
    int bid = blockIdx.x;                 // (bq*NSLAB+s)*KP1 + p
    int p  = bid % KP1;
    int s  = (bid / KP1) % NSLAB;
    int bq = bid / (KP1 * NSLAB);
    const float* Fq = fq + (size_t)bq * T_ * C_;
    int d0 = s * DT;
    for (int idx = threadIdx.x; idx < 16 * DT; idx += 256) {
        int k = idx >> 5, d = idx & 31;
        int t = p * 16 + k;
        tile[k][d] = (t < T_) ? SCALE * Fq[(size_t)t * C_ + d0 + d] : 0.f;
    }
    __syncthreads();
    u32* dst = g_A1 + (size_t)bid * A1_PANEL;
    for (int idx = threadIdx.x; idx < A1_PANEL; idx += 256) {
        int pl  = idx >> 8;
        int rem = idx & 255;
        int T   = rem >> 7;
        int lane = (rem >> 2) & 31;
        int reg  = idx & 3;
        int grr = lane >> 2, gcc = lane & 3;
        int dl = T * 16 + grr + ((reg & 1) ? 8 : 0);
        int kl = 2 * gcc + ((reg & 2) ? 8 : 0);
        float x0 = tile[kl][dl], x1 = tile[kl + 1][dl];
        dst[idx] = pl ? bpack_lo(x0, x1) : bpack_hi(x0, x1);
    }
}

// B1[k=t][n=c] = Fs[t][c], layout [G48][lane32][j4] j:0,1=hi 2,3=lo
__global__ void pack_b1(const float* __restrict__ fs) {
    __shared__ float tile[16][385];
    int bid = blockIdx.x;                 // bn*KP1 + p
    int p  = bid % KP1;
    int bn = bid / KP1;
    const float* Fs = fs + (size_t)bn * T_ * C_;
    for (int idx = threadIdx.x; idx < 16 * C_; idx += 256) {
        int k = idx / C_, c = idx % C_;
        int t = p * 16 + k;
        tile[k][c] = (t < T_) ? Fs[(size_t)t * C_ + c] : 0.f;
    }
    __syncthreads();
    u32* dst = g_B1 + (size_t)bid * B1_PANEL;
    for (int idx = threadIdx.x; idx < B1_PANEL; idx += 256) {
        int G    = idx >> 7;
        int lane = (idx >> 2) & 31;
        int j    = idx & 3;
        int pl   = j >> 1;
        int reg  = j & 1;
        int grr = lane >> 2, gcc = lane & 3;
        int n  = G * 8 + grr;
        int kl = 2 * gcc + 8 * reg;
        float x0 = tile[kl][n], x1 = tile[kl + 1][n];
        dst[idx] = pl ? bpack_lo(x0, x1) : bpack_hi(x0, x1);
    }
}

// B2[k=c][n=t] = Fq[t][c], layout [G25][lane32][j4]
__global__ void pack_b2(const float* __restrict__ fq) {
    __shared__ float tile[T_][17];
    int bid = blockIdx.x;                 // bq*KP2 + p
    int p  = bid % KP2;
    int bq = bid / KP2;
    const float* Fq = fq + (size_t)bq * T_ * C_;
    for (int idx = threadIdx.x; idx < T_ * 16; idx += 256) {
        int t = idx >> 4, c = idx & 15;
        tile[t][c] = Fq[(size_t)t * C_ + p * 16 + c];
    }
    __syncthreads();
    u32* dst = g_B2 + (size_t)bid * B2_PANEL;
    for (int idx = threadIdx.x; idx < B2_PANEL; idx += 256) {
        int G    = idx >> 7;
        int lane = (idx >> 2) & 31;
        int j    = idx & 3;
        int pl   = j >> 1;
        int reg  = j & 1;
        int grr = lane >> 2, gcc = lane & 3;
        int t  = G * 8 + grr;
        int kl = 2 * gcc + 8 * reg;
        float x0 = 0.f, x1 = 0.f;
        if (t < T_) { x0 = tile[t][kl]; x1 = tile[t][kl + 1]; }
        dst[idx] = pl ? bpack_lo(x0, x1) : bpack_hi(x0, x1);
    }
}

// Fs token L2 norms: one block per bn
__global__ void fsnorm_kernel(const float* __restrict__ fs) {
    int bn = blockIdx.x;
    int wid = threadIdx.x >> 5, lane = threadIdx.x & 31;
    const float* Fs = fs + (size_t)bn * T_ * C_;
    for (int r = wid; r < T_; r += 8) {
        float s = 0.f;
        #pragma unroll
        for (int u = 0; u < 12; u++) {
            float v = Fs[(size_t)r * C_ + lane + 32 * u];
            s += v * v;
        }
        #pragma unroll
        for (int o = 16; o > 0; o >>= 1) s += __shfl_xor_sync(0xffffffffu, s, o);
        if (lane == 0) g_nfs[bn * T_ + r] = sqrtf(s);
    }
}

// ==================== main kernel ====================

__global__ __launch_bounds__(TPB, 2)
void episodic_main(const float* __restrict__ fs_g) {
    extern __shared__ u32 smu[];
    float* smf = (float*)smu;
    const u32 smbase = (u32)__cvta_generic_to_shared(smu);

    const int cid = blockIdx.x;      // 0..1499
    const int bx = cid >> 1;         // episode index 0..749
    const int half = cid & 1;        // slab half
    const int nn = bx % N_;
    const int bq = bx / N_;          // b*75+q
    const int bb = bq / Q_;
    const int bn = bb * N_ + nn;
    const float* __restrict__ Fs = fs_g + (size_t)bn * T_ * C_;

    const int tid = threadIdx.x;
    const int wid = tid >> 5, lane = tid & 31;
    const int gr = lane >> 2, gc = lane & 3;
    // GEMM2 N split over 8 warps: wid0 -> 4 groups, others 3 (total 25)
    const int ng2 = (wid == 0) ? 4 : 3;
    const int g2base = (wid == 0) ? 0 : 4 + (wid - 1) * 3;

    for (int i = tid; i < NT2; i += TPB) { smf[U_PN + i] = 0.f; smf[U_PQ + i] = 0.f; }
    __syncthreads();

    const u32* gB1 = g_B1 + (size_t)bn * KP1 * B1_PANEL;
    const u32* gB2 = g_B2 + (size_t)bq * KP2 * B2_PANEL;

    for (int s = 0; s < HSLAB; s++) {
        const int slab = half * HSLAB + s;
        const int d0 = slab * DT;
        const u32* gA1 = g_A1 + (size_t)(bq * NSLAB + slab) * KP1 * A1_PANEL;

        // ---------------- GEMM1: S[32][384] ----------------
        float acc1[2][6][4];
        #pragma unroll
        for (int mt = 0; mt < 2; mt++)
            #pragma unroll
            for (int nt = 0; nt < 6; nt++)
                #pragma unroll
                for (int e = 0; e < 4; e++) acc1[mt][nt][e] = 0.f;

        {
            const float4* srcB = (const float4*)(gB1);
            u32 dstB = smbase + (U_B) * 4;
            #pragma unroll
            for (int j = 0; j < 6; j++) cp16(dstB + (tid + j * TPB) * 16, srcB + tid + j * TPB);
            if (tid < 128) {
                const float4* srcA = (const float4*)(gA1);
                cp16(smbase + (U_A1) * 4 + tid * 16, srcA + tid);
            }
            CP_COMMIT();
        }
        for (int p = 0; p < KP1; p++) {
            const int buf = p & 1;
            CP_WAIT0();
            __syncthreads();
            if (p + 1 < KP1) {
                const float4* srcB = (const float4*)(gB1 + (size_t)(p + 1) * B1_PANEL);
                u32 dstB = smbase + (U_B + (buf ^ 1) * B1_PANEL) * 4;
                #pragma unroll
                for (int j = 0; j < 6; j++) cp16(dstB + (tid + j * TPB) * 16, srcB + tid + j * TPB);
                if (tid < 128) {
                    const float4* srcA = (const float4*)(gA1 + (size_t)(p + 1) * A1_PANEL);
                    cp16(smbase + (U_A1 + (buf ^ 1) * A1_PANEL) * 4 + tid * 16, srcA + tid);
                }
                CP_COMMIT();
            }
            const u32* bA = smu + U_A1 + buf * A1_PANEL;
            const u32* bB = smu + U_B + buf * B1_PANEL;
            u32 ah[2][4], al[2][4];
            #pragma unroll
            for (int mt = 0; mt < 2; mt++) {
                uint4 h = *(const uint4*)&bA[((0 * 2 + mt) * 32 + lane) * 4];
                uint4 l = *(const uint4*)&bA[((1 * 2 + mt) * 32 + lane) * 4];
                ah[mt][0] = h.x; ah[mt][1] = h.y; ah[mt][2] = h.z; ah[mt][3] = h.w;
                al[mt][0] = l.x; al[mt][1] = l.y; al[mt][2] = l.z; al[mt][3] = l.w;
            }
            #pragma unroll
            for (int nt = 0; nt < 6; nt++) {
                int G = wid * 6 + nt;
                uint4 b4 = *(const uint4*)&bB[(G * 32 + lane) * 4];
                #pragma unroll
                for (int mt = 0; mt < 2; mt++) {
                    mma16(acc1[mt][nt], ah[mt], b4.x, b4.y);
                    mma16(acc1[mt][nt], ah[mt], b4.z, b4.w);
                    mma16(acc1[mt][nt], al[mt], b4.x, b4.y);
                }
            }
        }

        // ---------------- softmax (row max/sum across 8 warps) ----------------
        #pragma unroll
        for (int mt = 0; mt < 2; mt++)
            #pragma unroll
            for (int h = 0; h < 2; h++) {
                float mx = -INFINITY;
                #pragma unroll
                for (int nt = 0; nt < 6; nt++)
                    mx = fmaxf(mx, fmaxf(acc1[mt][nt][2 * h], acc1[mt][nt][2 * h + 1]));
                mx = fmaxf(mx, __shfl_xor_sync(0xffffffffu, mx, 1));
                mx = fmaxf(mx, __shfl_xor_sync(0xffffffffu, mx, 2));
                int row = mt * 16 + gr + 8 * h;
                if (gc == 0) smf[U_PMAX + row * 8 + wid] = mx;
            }
        __syncthreads();
        #pragma unroll
        for (int mt = 0; mt < 2; mt++)
            #pragma unroll
            for (int h = 0; h < 2; h++) {
                int row = mt * 16 + gr + 8 * h;
                float gmax = -INFINITY;
                #pragma unroll
                for (int w = 0; w < 8; w++)
                    gmax = fmaxf(gmax, smf[U_PMAX + row * 8 + w]);
                float s2 = 0.f;
                #pragma unroll
                for (int nt = 0; nt < 6; nt++) {
                    float v0 = __expf(acc1[mt][nt][2 * h] - gmax);
                    float v1 = __expf(acc1[mt][nt][2 * h + 1] - gmax);
                    acc1[mt][nt][2 * h] = v0;
                    acc1[mt][nt][2 * h + 1] = v1;
                    s2 += v0 + v1;
                }
                s2 += __shfl_xor_sync(0xffffffffu, s2, 1);
                s2 += __shfl_xor_sync(0xffffffffu, s2, 2);
                if (gc == 0) smf[U_PSUM + row * 8 + wid] = s2;
            }
        __syncthreads();
        if (wid == 0 && gc == 0) {
            #pragma unroll
            for (int mt = 0; mt < 2; mt++)
                #pragma unroll
                for (int h = 0; h < 2; h++) {
                    int row = mt * 16 + gr + 8 * h;
                    float tot = 0.f;
                    #pragma unroll
                    for (int w = 0; w < 8; w++) tot += smf[U_PSUM + row * 8 + w];
                    smf[U_RINV + row] = 1.0f / tot;
                }
        }

        // pack Pexp into GEMM2 A-fragment layout (hi/lo, STS.128)
        #pragma unroll
        for (int mt = 0; mt < 2; mt++) {
            #pragma unroll
            for (int np = 0; np < 3; np++) {
                int G0 = wid * 6 + 2 * np;
                int p  = G0 >> 1;
                u32 vh[4], vl[4];
                bsplit2(acc1[mt][2 * np][0], acc1[mt][2 * np][1], vh[0], vl[0]);
                bsplit2(acc1[mt][2 * np][2], acc1[mt][2 * np][3], vh[1], vl[1]);
                bsplit2(acc1[mt][2 * np + 1][0], acc1[mt][2 * np + 1][1], vh[2], vl[2]);
                bsplit2(acc1[mt][2 * np + 1][2], acc1[mt][2 * np + 1][3], vh[3], vl[3]);
                *(uint4*)&smu[U_A2 + (((p * 2 + 0) * 2 + mt) * 32 + lane) * 4] =
                    make_uint4(vh[0], vh[1], vh[2], vh[3]);
                *(uint4*)&smu[U_A2 + (((p * 2 + 1) * 2 + mt) * 32 + lane) * 4] =
                    make_uint4(vl[0], vl[1], vl[2], vl[3]);
            }
        }
        __syncthreads();

        // ---------------- GEMM2: fq_new^T[32][200] ----------------
        float acc2[2][4][4];
        #pragma unroll
        for (int mt = 0; mt < 2; mt++)
            #pragma unroll
            for (int nt = 0; nt < 4; nt++)
                #pragma unroll
                for (int e = 0; e < 4; e++) acc2[mt][nt][e] = 0.f;

        {
            const float4* srcB = (const float4*)(gB2);
            u32 dstB = smbase + (U_B) * 4;
            #pragma unroll
            for (int j = 0; j < 4; j++) {
                int i = tid + j * TPB;
                if (i < 800) cp16(dstB + i * 16, srcB + i);
            }
            CP_COMMIT();
        }
        for (int p = 0; p < KP2; p++) {
            const int buf = p & 1;
            CP_WAIT0();
            __syncthreads();
            if (p + 1 < KP2) {
                const float4* srcB = (const float4*)(gB2 + (size_t)(p + 1) * B2_PANEL);
                u32 dstB = smbase + (U_B + (buf ^ 1) * B1_PANEL) * 4;
                #pragma unroll
                for (int j = 0; j < 4; j++) {
                    int i = tid + j * TPB;
                    if (i < 800) cp16(dstB + i * 16, srcB + i);
                }
                CP_COMMIT();
            }
            const u32* bB = smu + U_B + buf * B1_PANEL;
            u32 ah[2][4], al[2][4];
            #pragma unroll
            for (int mt = 0; mt < 2; mt++) {
                uint4 h = *(const uint4*)&smu[U_A2 + (((p * 2 + 0) * 2 + mt) * 32 + lane) * 4];
                uint4 l = *(const uint4*)&smu[U_A2 + (((p * 2 + 1) * 2 + mt) * 32 + lane) * 4];
                ah[mt][0] = h.x; ah[mt][1] = h.y; ah[mt][2] = h.z; ah[mt][3] = h.w;
                al[mt][0] = l.x; al[mt][1] = l.y; al[mt][2] = l.z; al[mt][3] = l.w;
            }
            for (int nt = 0; nt < ng2; nt++) {
                int G = g2base + nt;
                uint4 b4 = *(const uint4*)&bB[(G * 32 + lane) * 4];
                #pragma unroll
                for (int mt = 0; mt < 2; mt++) {
                    mma16(acc2[mt][nt], ah[mt], b4.x, b4.y);
                    mma16(acc2[mt][nt], ah[mt], b4.z, b4.w);
                    mma16(acc2[mt][nt], al[mt], b4.x, b4.y);
                }
            }
        }
        __syncthreads();

        // ---------------- epilogue: rinv, num/norm2 partials ----------------
        for (int nt = 0; nt < ng2; nt++) {
            int G = g2base + nt;
            int ta = G * 8 + 2 * gc;
            int tb = ta + 1;
            float pn_a = 0.f, pq_a = 0.f, pn_b = 0.f, pq_b = 0.f;
            #pragma unroll
            for (int mt = 0; mt < 2; mt++) {
                int rb1 = mt * 16 + gr;
                int rb2 = rb1 + 8;
                float r1 = smf[U_RINV + rb1];
                float r2 = smf[U_RINV + rb2];
                float v0 = acc2[mt][nt][0] * r1;
                float v1 = acc2[mt][nt][1] * r1;
                float v2 = acc2[mt][nt][2] * r2;
                float v3 = acc2[mt][nt][3] * r2;
                int gd1 = d0 + rb1, gd2 = d0 + rb2;
                float fa1 = 0.f, fa2 = 0.f, fb1 = 0.f, fb2 = 0.f;
                if (ta < T_) { fa1 = Fs[(size_t)ta * C_ + gd1]; fa2 = Fs[(size_t)ta * C_ + gd2]; }
                if (tb < T_) { fb1 = Fs[(size_t)tb * C_ + gd1]; fb2 = Fs[(size_t)tb * C_ + gd2]; }
                pn_a += v0 * fa1 + v2 * fa2;
                pq_a += v0 * v0 + v2 * v2;
                pn_b += v1 * fb1 + v3 * fb2;
                pq_b += v1 * v1 + v3 * v3;
            }
            #pragma unroll
            for (int o = 4; o <= 16; o <<= 1) {
                pn_a += __shfl_xor_sync(0xffffffffu, pn_a, o);
                pq_a += __shfl_xor_sync(0xffffffffu, pq_a, o);
                pn_b += __shfl_xor_sync(0xffffffffu, pn_b, o);
                pq_b += __shfl_xor_sync(0xffffffffu, pq_b, o);
            }
            if (lane < 4) {
                smf[U_PN + ta] += pn_a;
                smf[U_PQ + ta] += pq_a;
                smf[U_PN + tb] += pn_b;
                smf[U_PQ + tb] += pq_b;
            }
        }
        __syncthreads();
    }  // slab loop

    // write partials to gmem
    if (tid < NT2) {
        g_pn[(size_t)cid * NT2 + tid] = smf[U_PN + tid];
        g_pq[(size_t)cid * NT2 + tid] = smf[U_PQ + tid];
    }
}

// ==================== reduce / epilogue kernels ====================

// one warp per episode: combine halves, cosine, top1 max
__global__ void top1_kernel() {
    int w = (blockIdx.x * blockDim.x + threadIdx.x) >> 5;
    int lane = threadIdx.x & 31;
    if (w >= B_ * Q_ * N_) return;
    int nn = w % N_;
    int bq = w / N_;
    int bb = bq / Q_;
    int bn = bb * N_ + nn;
    float local = -INFINITY;
    for (int t = lane; t < T_; t += 32) {
        float num = g_pn[(size_t)(2 * w) * NT2 + t] + g_pn[(size_t)(2 * w + 1) * NT2 + t];
        float nrm = g_pq[(size_t)(2 * w) * NT2 + t] + g_pq[(size_t)(2 * w + 1) * NT2 + t];
        float denom = fmaxf(sqrtf(nrm) * g_nfs[bn * T_ + t], 1e-8f);
        local = fmaxf(local, num / denom);
    }
    #pragma unroll
    for (int o = 16; o > 0; o >>= 1)
        local = fmaxf(local, __shfl_xor_sync(0xffffffffu, local, o));
    if (lane == 0) g_top1[w] = local;
}

__global__ void finalize_logits_kernel(float* __restrict__ out) {
    int i = blockIdx.x * blockDim.x + threadIdx.x;
    if (i < B_ * Q_) {
        float s = 0.f;
        #pragma unroll
        for (int n = 0; n < N_; n++) s += g_top1[i * N_ + n];
        out[i] = s * (1.0f / N_);
    }
}

__global__ void cls_kernel(const float* __restrict__ xq,
                           const float* __restrict__ xs,
                           float* __restrict__ out) {
    int w = (blockIdx.x * blockDim.x + threadIdx.x) >> 5;
    int lid = threadIdx.x & 31;
    if (w >= B_ * Q_ * N_) return;
    int nn = w % N_;
    int qq = (w / N_) % Q_;
    int bb = w / (N_ * Q_);
    const float* q = xq + (size_t)(bb * Q_ + qq) * D_;
    const float* s = xs + (size_t)(bb * N_ + nn) * D_;
    float dot = 0.f, nq = 0.f, ns = 0.f;
    #pragma unroll
    for (int u = 0; u < D_ / 32; u++) {
        float a = q[lid + 32 * u];
        float b = s[lid + 32 * u];
        dot += a * b;
        nq += a * a;
        ns += b * b;
    }
    #pragma unroll
    for (int o = 16; o > 0; o >>= 1) {
        dot += __shfl_xor_sync(0xffffffffu, dot, o);
        nq  += __shfl_xor_sync(0xffffffffu, nq, o);
        ns  += __shfl_xor_sync(0xffffffffu, ns, o);
    }
    if (lid == 0) {
        float den = fmaxf(sqrtf(nq), 1e-12f) * fmaxf(sqrtf(ns), 1e-12f);
        out[B_ * Q_ + w] = 10.0f * dot / den;
    }
}

extern "C" void kernel_launch(void* const* d_in, const int* in_sizes, int n_in,
                              void* d_out, int out_size) {
    const float* fq = (const float*)d_in[0];  // (2,75,196,384)
    const float* fs = (const float*)d_in[1];  // (2,5,1,196,384)
    const float* xq = (const float*)d_in[2];  // (2,75,384)
    const float* xs = (const float*)d_in[3];  // (2,5,1,384)
    float* out = (float*)d_out;               // [150 logits][750 cls_logits]

    pack_a1<<<150 * NSLAB * KP1, 256>>>(fq);
    pack_b1<<<10 * KP1, 256>>>(fs);
    pack_b2<<<150 * KP2, 256>>>(fq);
    fsnorm_kernel<<<10, 256>>>(fs);

    const size_t smem_bytes = (size_t)U_TOT * sizeof(u32);
    cudaFuncSetAttribute(episodic_main,
                         cudaFuncAttributeMaxDynamicSharedMemorySize,
                         (int)smem_bytes);
    episodic_main<<<1500, TPB, smem_bytes>>>(fs);

    top1_kernel<<<(B_ * Q_ * N_ * 32 + 255) / 256, 256>>>();
    finalize_logits_kernel<<<1, 256>>>(out);
    cls_kernel<<<(B_ * Q_ * N_ * 32 + 255) / 256, 256>>>(xq, xs, out);
}